// round 2
// baseline (speedup 1.0000x reference)
#include <cuda_runtime.h>
#include <math.h>

#define BB 2
#define NN 4096
#define DD 256
#define HH 8
#define DH 32
#define ROWS (BB*NN)
#define BH (BB*HH)

#define TQ 128   // queries per block
#define TK 128   // keys per shared tile

// Scratch: head-split [B*H, N, DH] fp32 layouts (8 MB each). Device globals
// per allocation rules.
__device__ float g_q[BH * NN * DH];
__device__ float g_k[BH * NN * DH];
__device__ float g_v[BH * NN * DH];

// ---------------------------------------------------------------------------
// Projection: out = x @ W^T + b, written into head-split layout.
// grid = (DD/64, ROWS/64, 3); z selects which projection.
// 256 threads, 64x64 output tile, 4x4 per thread, k-chunks of 16.
// ---------------------------------------------------------------------------
__global__ __launch_bounds__(256) void proj_kernel(
    const float* __restrict__ xq, const float* __restrict__ xkv,
    const float* __restrict__ Wq, const float* __restrict__ bq,
    const float* __restrict__ Wk, const float* __restrict__ bk,
    const float* __restrict__ Wv, const float* __restrict__ bv)
{
    const float* x;
    const float* W;
    const float* bias;
    float* out;
    int which = blockIdx.z;
    if (which == 0)      { x = xq;  W = Wq; bias = bq; out = g_q; }
    else if (which == 1) { x = xkv; W = Wk; bias = bk; out = g_k; }
    else                 { x = xkv; W = Wv; bias = bv; out = g_v; }

    __shared__ float xs[64][17];
    __shared__ float ws[64][17];

    int tid  = threadIdx.x;
    int row0 = blockIdx.y * 64;
    int col0 = blockIdx.x * 64;
    int tr = tid / 16;   // 0..15
    int tc = tid % 16;   // 0..15

    float acc[4][4];
#pragma unroll
    for (int i = 0; i < 4; i++)
#pragma unroll
        for (int j = 0; j < 4; j++) acc[i][j] = 0.f;

    for (int k0 = 0; k0 < DD; k0 += 16) {
        // load 64x16 x-tile and 64x16 W-tile (W rows = output cols, since W^T)
#pragma unroll 4
        for (int i = tid; i < 64 * 16; i += 256) {
            int r = i / 16, c = i % 16;
            xs[r][c] = x[(size_t)(row0 + r) * DD + k0 + c];
            ws[r][c] = W[(size_t)(col0 + r) * DD + k0 + c];
        }
        __syncthreads();
#pragma unroll
        for (int kk = 0; kk < 16; kk++) {
            float a[4], b[4];
#pragma unroll
            for (int i = 0; i < 4; i++) a[i] = xs[tr * 4 + i][kk];
#pragma unroll
            for (int j = 0; j < 4; j++) b[j] = ws[tc * 4 + j][kk];
#pragma unroll
            for (int i = 0; i < 4; i++)
#pragma unroll
                for (int j = 0; j < 4; j++) acc[i][j] += a[i] * b[j];
        }
        __syncthreads();
    }

#pragma unroll
    for (int i = 0; i < 4; i++) {
        int r = row0 + tr * 4 + i;
        int b_ = r / NN, n = r % NN;
#pragma unroll
        for (int j = 0; j < 4; j++) {
            int c = col0 + tc * 4 + j;
            int h = c / DH, dcol = c % DH;
            out[((size_t)(b_ * HH + h) * NN + n) * DH + dcol] = acc[i][j] + bias[c];
        }
    }
}

// ---------------------------------------------------------------------------
// Flash attention (fp32 scalar): grid = (N/TQ, B*H), 128 threads.
// One thread = one query. q, o, score-chunk live in registers.
// K/V tiles (TK x DH) staged in shared; all threads walk the same key index
// so shared reads are broadcasts (conflict-free).
// ---------------------------------------------------------------------------
__global__ __launch_bounds__(128) void attn_kernel(float* __restrict__ out)
{
    __shared__ float Ks[TK * DH];
    __shared__ float Vs[TK * DH];

    int bh  = blockIdx.y;
    int tid = threadIdx.x;
    int qi  = blockIdx.x * TQ + tid;

    const float scale = rsqrtf((float)DH);
    const float* qptr = g_q + ((size_t)bh * NN + qi) * DH;

    float q[DH];
#pragma unroll
    for (int d = 0; d < DH; d++) q[d] = qptr[d] * scale;

    float o[DH];
#pragma unroll
    for (int d = 0; d < DH; d++) o[d] = 0.f;
    float m = -INFINITY, l = 0.f;

    const float* Kbase = g_k + (size_t)bh * NN * DH;
    const float* Vbase = g_v + (size_t)bh * NN * DH;

    for (int k0 = 0; k0 < NN; k0 += TK) {
        __syncthreads();
        const float4* Kg = (const float4*)(Kbase + (size_t)k0 * DH);
        const float4* Vg = (const float4*)(Vbase + (size_t)k0 * DH);
        float4* Ks4 = (float4*)Ks;
        float4* Vs4 = (float4*)Vs;
#pragma unroll
        for (int i = tid; i < TK * DH / 4; i += TQ) {
            Ks4[i] = Kg[i];
            Vs4[i] = Vg[i];
        }
        __syncthreads();

        // process tile in chunks of 32 keys; scores for a chunk in registers
        for (int c0 = 0; c0 < TK; c0 += 32) {
            float s[32];
            float cmax = -INFINITY;
#pragma unroll
            for (int j = 0; j < 32; j++) {
                const float* kr = Ks + (c0 + j) * DH;
                float acc = 0.f;
#pragma unroll
                for (int d = 0; d < DH; d++) acc += q[d] * kr[d];
                s[j] = acc;
                cmax = fmaxf(cmax, acc);
            }
            float mnew = fmaxf(m, cmax);
            float corr = __expf(m - mnew);
            m = mnew;
            l *= corr;
#pragma unroll
            for (int d = 0; d < DH; d++) o[d] *= corr;
#pragma unroll
            for (int j = 0; j < 32; j++) {
                float p = __expf(s[j] - m);
                l += p;
                const float* vr = Vs + (c0 + j) * DH;
#pragma unroll
                for (int d = 0; d < DH; d++) o[d] += p * vr[d];
            }
        }
    }

    int b_ = bh / HH, h = bh % HH;
    float inv = 1.f / l;
    float* op = out + ((size_t)b_ * NN + qi) * DD + h * DH;
#pragma unroll
    for (int d = 0; d < DH; d++) op[d] = o[d] * inv;
}

extern "C" void kernel_launch(void* const* d_in, const int* in_sizes, int n_in,
                              void* d_out, int out_size)
{
    const float* x_q  = (const float*)d_in[0];
    const float* x_kv = (const float*)d_in[1];
    const float* Wq   = (const float*)d_in[2];
    const float* bq   = (const float*)d_in[3];
    const float* Wk   = (const float*)d_in[4];
    const float* bk   = (const float*)d_in[5];
    const float* Wv   = (const float*)d_in[6];
    const float* bv   = (const float*)d_in[7];
    float* out = (float*)d_out;

    dim3 pgrid(DD / 64, ROWS / 64, 3);
    proj_kernel<<<pgrid, 256>>>(x_q, x_kv, Wq, bq, Wk, bk, Wv, bv);

    dim3 agrid(NN / TQ, BH);
    attn_kernel<<<agrid, 128>>>(out);
}

// round 4
// speedup vs baseline: 2.9270x; 2.9270x over previous
#include <cuda_runtime.h>
#include <cuda_bf16.h>
#include <math.h>
#include <stdint.h>

#define BB 2
#define NN 4096
#define DD 256
#define HH 8
#define DH 32
#define ROWS (BB*NN)
#define BH (BB*HH)

// fp32 head-split scratch [B*H, N, DH]
__device__ float g_q[BH * NN * DH];
__device__ float g_k[BH * NN * DH];
__device__ float g_v[BH * NN * DH];

// ---------------------------------------------------------------------------
// helpers
// ---------------------------------------------------------------------------
// bf16 hi/lo split of a float pair, packed as two bf16x2 words
__device__ __forceinline__ void split2(float a, float b, uint32_t& hi, uint32_t& lo) {
    __nv_bfloat16 ah = __float2bfloat16(a), bh = __float2bfloat16(b);
    __nv_bfloat16 al = __float2bfloat16(a - __bfloat162float(ah));
    __nv_bfloat16 bl = __float2bfloat16(b - __bfloat162float(bh));
    __nv_bfloat162 h; h.x = ah; h.y = bh;
    __nv_bfloat162 l; l.x = al; l.y = bl;
    hi = *reinterpret_cast<uint32_t*>(&h);
    lo = *reinterpret_cast<uint32_t*>(&l);
}

// m16n8k16 row.col bf16 -> f32 accumulate (HMMA; valid on compute_103 target)
__device__ __forceinline__ void mma16816(float* c, const uint32_t* a,
                                         uint32_t b0, uint32_t b1) {
    asm volatile(
        "mma.sync.aligned.m16n8k16.row.col.f32.bf16.bf16.f32 "
        "{%0,%1,%2,%3}, {%4,%5,%6,%7}, {%8,%9}, {%0,%1,%2,%3};"
        : "+f"(c[0]), "+f"(c[1]), "+f"(c[2]), "+f"(c[3])
        : "r"(a[0]), "r"(a[1]), "r"(a[2]), "r"(a[3]), "r"(b0), "r"(b1));
}

// ---------------------------------------------------------------------------
// Projection (unchanged): out = x @ W^T + b into head-split layout
// ---------------------------------------------------------------------------
__global__ __launch_bounds__(256) void proj_kernel(
    const float* __restrict__ xq, const float* __restrict__ xkv,
    const float* __restrict__ Wq, const float* __restrict__ bq,
    const float* __restrict__ Wk, const float* __restrict__ bk,
    const float* __restrict__ Wv, const float* __restrict__ bv)
{
    const float* x; const float* W; const float* bias; float* out;
    int which = blockIdx.z;
    if (which == 0)      { x = xq;  W = Wq; bias = bq; out = g_q; }
    else if (which == 1) { x = xkv; W = Wk; bias = bk; out = g_k; }
    else                 { x = xkv; W = Wv; bias = bv; out = g_v; }

    __shared__ float xs[64][17];
    __shared__ float ws[64][17];

    int tid = threadIdx.x;
    int row0 = blockIdx.y * 64, col0 = blockIdx.x * 64;
    int tr = tid / 16, tc = tid % 16;

    float acc[4][4];
#pragma unroll
    for (int i = 0; i < 4; i++)
#pragma unroll
        for (int j = 0; j < 4; j++) acc[i][j] = 0.f;

    for (int k0 = 0; k0 < DD; k0 += 16) {
#pragma unroll 4
        for (int i = tid; i < 64 * 16; i += 256) {
            int r = i / 16, c = i % 16;
            xs[r][c] = x[(size_t)(row0 + r) * DD + k0 + c];
            ws[r][c] = W[(size_t)(col0 + r) * DD + k0 + c];
        }
        __syncthreads();
#pragma unroll
        for (int kk = 0; kk < 16; kk++) {
            float a[4], b[4];
#pragma unroll
            for (int i = 0; i < 4; i++) a[i] = xs[tr * 4 + i][kk];
#pragma unroll
            for (int j = 0; j < 4; j++) b[j] = ws[tc * 4 + j][kk];
#pragma unroll
            for (int i = 0; i < 4; i++)
#pragma unroll
                for (int j = 0; j < 4; j++) acc[i][j] += a[i] * b[j];
        }
        __syncthreads();
    }
#pragma unroll
    for (int i = 0; i < 4; i++) {
        int r = row0 + tr * 4 + i;
        int b_ = r / NN, n = r % NN;
#pragma unroll
        for (int j = 0; j < 4; j++) {
            int c = col0 + tc * 4 + j;
            int h = c / DH, dcol = c % DH;
            out[((size_t)(b_ * HH + h) * NN + n) * DH + dcol] = acc[i][j] + bias[c];
        }
    }
}

// ---------------------------------------------------------------------------
// FlashAttention-2 with warp-level mma.sync (bf16 hi/lo 3-term).
// Block: 256 threads = 8 warps; 128 queries of one (b,h); 64-key tiles.
// Warp w owns query rows [w*16, w*16+16).
// K smem:  [64 keys][32 dh] bf16 hi/lo, row stride 40 halfs (80B, pad).
// Vt smem: [32 dh][64 keys] bf16 hi/lo, row stride 70 halfs (140B, pad).
// ---------------------------------------------------------------------------
#define KSTRW 20   // K row stride in 32-bit words
#define VSTRW 35   // Vt row stride in 32-bit words

__global__ __launch_bounds__(256) void attn_mma(float* __restrict__ out)
{
    __shared__ uint32_t Kh32[64 * KSTRW];
    __shared__ uint32_t Kl32[64 * KSTRW];
    __shared__ uint32_t Vh32[32 * VSTRW];
    __shared__ uint32_t Vl32[32 * VSTRW];

    int tid = threadIdx.x;
    int warp = tid >> 5, lane = tid & 31;
    int g = lane >> 2, i4 = lane & 3;
    int bh = blockIdx.y;
    int q0 = blockIdx.x * 128;
    int b_ = bh >> 3, h = bh & 7;

    // scale folds 1/sqrt(dh) and log2(e) (softmax uses exp2)
    const float SC = 1.4426950408889634f * 0.17677669529663687f;

    // --- persistent Q fragments (hi/lo), A-layout for m16n8k16 ---
    uint32_t qh[2][4], ql[2][4];
    {
        const float* qp0 = g_q + ((size_t)bh * NN + q0 + warp * 16 + g) * DH;
        const float* qp1 = qp0 + 8 * DH;
#pragma unroll
        for (int kt = 0; kt < 2; kt++) {
            int c = 16 * kt + 2 * i4;
            float2 v00 = *(const float2*)(qp0 + c);
            float2 v10 = *(const float2*)(qp1 + c);
            float2 v01 = *(const float2*)(qp0 + c + 8);
            float2 v11 = *(const float2*)(qp1 + c + 8);
            split2(v00.x * SC, v00.y * SC, qh[kt][0], ql[kt][0]);
            split2(v10.x * SC, v10.y * SC, qh[kt][1], ql[kt][1]);
            split2(v01.x * SC, v01.y * SC, qh[kt][2], ql[kt][2]);
            split2(v11.x * SC, v11.y * SC, qh[kt][3], ql[kt][3]);
        }
    }

    float O[4][4];
#pragma unroll
    for (int a = 0; a < 4; a++)
#pragma unroll
        for (int b = 0; b < 4; b++) O[a][b] = 0.f;
    float m0 = -INFINITY, m1 = -INFINITY, l0 = 0.f, l1 = 0.f;

    const float* Kb = g_k + (size_t)bh * NN * DH;
    const float* Vb = g_v + (size_t)bh * NN * DH;

    for (int k0 = 0; k0 < NN; k0 += 64) {
        __syncthreads();
        // ---- stage K (hi/lo) and V^T (hi/lo) tiles ----
#pragma unroll
        for (int it = 0; it < 2; it++) {
            int idx = tid + it * 256;
            int row = idx >> 3, c4 = (idx & 7) * 4;
            float4 f = *(const float4*)(Kb + (size_t)(k0 + row) * DH + c4);
            uint32_t hh, ll;
            split2(f.x, f.y, hh, ll);
            Kh32[row * KSTRW + (c4 >> 1)] = hh;
            Kl32[row * KSTRW + (c4 >> 1)] = ll;
            split2(f.z, f.w, hh, ll);
            Kh32[row * KSTRW + (c4 >> 1) + 1] = hh;
            Kl32[row * KSTRW + (c4 >> 1) + 1] = ll;

            float4 fv = *(const float4*)(Vb + (size_t)(k0 + row) * DH + c4);
            float vv[4] = {fv.x, fv.y, fv.z, fv.w};
#pragma unroll
            for (int j = 0; j < 4; j++) {
                __nv_bfloat16 vh = __float2bfloat16(vv[j]);
                __nv_bfloat16 vl = __float2bfloat16(vv[j] - __bfloat162float(vh));
                ((__nv_bfloat16*)Vh32)[(c4 + j) * (2 * VSTRW) + row] = vh;
                ((__nv_bfloat16*)Vl32)[(c4 + j) * (2 * VSTRW) + row] = vl;
            }
        }
        __syncthreads();

        // ---- S = Q K^T  (hi*hi + hi*lo + lo*hi) ----
        float S[8][4];
#pragma unroll
        for (int nt = 0; nt < 8; nt++) {
            S[nt][0] = S[nt][1] = S[nt][2] = S[nt][3] = 0.f;
            int kbase = (8 * nt + g) * KSTRW + i4;
            uint32_t kh0 = Kh32[kbase],      kh1 = Kh32[kbase + 4];
            uint32_t kh2 = Kh32[kbase + 8],  kh3 = Kh32[kbase + 12];
            uint32_t kl0 = Kl32[kbase],      kl1 = Kl32[kbase + 4];
            uint32_t kl2 = Kl32[kbase + 8],  kl3 = Kl32[kbase + 12];
            mma16816(S[nt], qh[0], kh0, kh1);
            mma16816(S[nt], qh[1], kh2, kh3);
            mma16816(S[nt], ql[0], kh0, kh1);
            mma16816(S[nt], ql[1], kh2, kh3);
            mma16816(S[nt], qh[0], kl0, kl1);
            mma16816(S[nt], qh[1], kl2, kl3);
        }

        // ---- online softmax (rows g and g+8) ----
        float mx0 = -INFINITY, mx1 = -INFINITY;
#pragma unroll
        for (int nt = 0; nt < 8; nt++) {
            mx0 = fmaxf(mx0, fmaxf(S[nt][0], S[nt][1]));
            mx1 = fmaxf(mx1, fmaxf(S[nt][2], S[nt][3]));
        }
        mx0 = fmaxf(mx0, __shfl_xor_sync(0xffffffffu, mx0, 1));
        mx0 = fmaxf(mx0, __shfl_xor_sync(0xffffffffu, mx0, 2));
        mx1 = fmaxf(mx1, __shfl_xor_sync(0xffffffffu, mx1, 1));
        mx1 = fmaxf(mx1, __shfl_xor_sync(0xffffffffu, mx1, 2));

        float mn0 = fmaxf(m0, mx0), mn1 = fmaxf(m1, mx1);
        float cr0 = exp2f(m0 - mn0), cr1 = exp2f(m1 - mn1);
        m0 = mn0; m1 = mn1;
        l0 *= cr0; l1 *= cr1;
#pragma unroll
        for (int nt2 = 0; nt2 < 4; nt2++) {
            O[nt2][0] *= cr0; O[nt2][1] *= cr0;
            O[nt2][2] *= cr1; O[nt2][3] *= cr1;
        }

        uint32_t pah[4][4], pal[4][4];
        float ls0 = 0.f, ls1 = 0.f;
#pragma unroll
        for (int nt = 0; nt < 8; nt++) {
            float p0 = exp2f(S[nt][0] - m0);
            float p1 = exp2f(S[nt][1] - m0);
            float p2 = exp2f(S[nt][2] - m1);
            float p3 = exp2f(S[nt][3] - m1);
            ls0 += p0 + p1; ls1 += p2 + p3;
            int kt = nt >> 1, sub = (nt & 1) * 2;
            split2(p0, p1, pah[kt][sub],     pal[kt][sub]);
            split2(p2, p3, pah[kt][sub + 1], pal[kt][sub + 1]);
        }
        l0 += ls0; l1 += ls1;

        // ---- O += P V  (hi*hi + lo*hi + hi*lo) ----
#pragma unroll
        for (int nt2 = 0; nt2 < 4; nt2++) {
            int vbase = (8 * nt2 + g) * VSTRW + i4;
#pragma unroll
            for (int kt = 0; kt < 4; kt++) {
                uint32_t v0 = Vh32[vbase + 8 * kt], v1 = Vh32[vbase + 8 * kt + 4];
                uint32_t w0 = Vl32[vbase + 8 * kt], w1 = Vl32[vbase + 8 * kt + 4];
                mma16816(O[nt2], pah[kt], v0, v1);
                mma16816(O[nt2], pal[kt], v0, v1);
                mma16816(O[nt2], pah[kt], w0, w1);
            }
        }
    }

    // ---- final l reduction + write ----
    l0 += __shfl_xor_sync(0xffffffffu, l0, 1);
    l0 += __shfl_xor_sync(0xffffffffu, l0, 2);
    l1 += __shfl_xor_sync(0xffffffffu, l1, 1);
    l1 += __shfl_xor_sync(0xffffffffu, l1, 2);
    float inv0 = 1.f / l0, inv1 = 1.f / l1;

    float* op0 = out + ((size_t)b_ * NN + q0 + warp * 16 + g) * DD + h * DH;
    float* op1 = op0 + 8 * DD;
#pragma unroll
    for (int nt2 = 0; nt2 < 4; nt2++) {
        float2 r0 = {O[nt2][0] * inv0, O[nt2][1] * inv0};
        float2 r1 = {O[nt2][2] * inv1, O[nt2][3] * inv1};
        *(float2*)(op0 + 8 * nt2 + 2 * i4) = r0;
        *(float2*)(op1 + 8 * nt2 + 2 * i4) = r1;
    }
}

extern "C" void kernel_launch(void* const* d_in, const int* in_sizes, int n_in,
                              void* d_out, int out_size)
{
    const float* x_q  = (const float*)d_in[0];
    const float* x_kv = (const float*)d_in[1];
    const float* Wq   = (const float*)d_in[2];
    const float* bq   = (const float*)d_in[3];
    const float* Wk   = (const float*)d_in[4];
    const float* bk   = (const float*)d_in[5];
    const float* Wv   = (const float*)d_in[6];
    const float* bv   = (const float*)d_in[7];
    float* out = (float*)d_out;

    dim3 pgrid(DD / 64, ROWS / 64, 3);
    proj_kernel<<<pgrid, 256>>>(x_q, x_kv, Wq, bq, Wk, bk, Wv, bv);

    dim3 agrid(NN / 128, BH);
    attn_mma<<<agrid, 256>>>(out);
}